// round 14
// baseline (speedup 1.0000x reference)
#include <cuda_runtime.h>
#include <cuda_bf16.h>

// loss = -(1/B) * sum_b [ 1 / (sum_j sigmoid(x[b,j] - x[b,0]) + 0.5) ]
// B = 32, N = 2048. Only row i=0 of the reference's [B,N,N] pair matrix is
// used, so compute the O(B*N) reduction directly.
//
// Two graph nodes overlapped via PDL (programmatic dependent launch):
//  - node A zeroes out[0] (1 thread), fences, triggers programmatic launch
//    completion. Replay-safe: out is re-zeroed every replay.
//  - node B (launched with ProgrammaticStreamSerialization) starts while A is
//    still in flight; each of its 32 blocks reduces one row, and tid 0 calls
//    cudaGridDependencySynchronize() (released as soon as A triggers — A is
//    ~instant) before a fire-and-forget atomicAdd(out, part). The return
//    value is unused, so ptxas emits REDG: no 318-cycle ATOMG-return wait on
//    any block's tail, which was the measured 0.25 us cost of every
//    single-node winner-detection scheme (R9/R11/R13).
//  - If the PDL attribute is not honored during capture, execution falls back
//    to plain stream order == the R5 two-node kernel (correct, 6.62 us).
//
// In-block path: 2 front-batched float4 loads per thread (MLP=2), sigmoid
// sums in two accumulators (halved FADD chain), per-thread sum quantized to
// 2^19 fixed point -> redux.sync.add.s32 one-op warp reduce (redux.f32 is
// illegal on sm_103, R10), int32 smem combine (block total <= 2^30: safe;
// R12's 2^22 scale overflowed int32).

#define RB 32
#define TQ_SCALE 524288.0f        /* 2^19 */
#define TQ_INV   (1.0f / 524288.0f)

static __global__ void rankloss_init(float* __restrict__ out) {
    out[0] = 0.0f;
    __threadfence();
    cudaTriggerProgrammaticLaunchCompletion();
}

static __global__ void __launch_bounds__(256) rankloss_main(
    const float* __restrict__ x, float* __restrict__ out, float inv_B)
{
    const int b   = blockIdx.x;
    const int tid = threadIdx.x;
    const float* row = x + (size_t)b * 2048;

    const float x0 = __ldg(row);

    // 2048 floats = 512 float4; 256 threads -> 2 loads each, front-batched.
    const float4* row4 = reinterpret_cast<const float4*>(row);
    float4 v0 = __ldg(row4 + tid);
    float4 v1 = __ldg(row4 + tid + 256);

    // sigmoid(v - x0) = 1 / (1 + exp(x0 - v)); two accumulators halve the
    // dependent-FADD chain.
    float s0 = 0.0f, s1 = 0.0f;
    s0 += __fdividef(1.0f, 1.0f + __expf(x0 - v0.x));
    s1 += __fdividef(1.0f, 1.0f + __expf(x0 - v0.y));
    s0 += __fdividef(1.0f, 1.0f + __expf(x0 - v0.z));
    s1 += __fdividef(1.0f, 1.0f + __expf(x0 - v0.w));
    s0 += __fdividef(1.0f, 1.0f + __expf(x0 - v1.x));
    s1 += __fdividef(1.0f, 1.0f + __expf(x0 - v1.y));
    s0 += __fdividef(1.0f, 1.0f + __expf(x0 - v1.z));
    s1 += __fdividef(1.0f, 1.0f + __expf(x0 - v1.w));
    float s = s0 + s1;

    // Quantize (s in (0,8] -> si <= 2^22; warp sum <= 2^27; block <= 2^30),
    // one-instruction warp reduction.
    int si = __float2int_rn(s * TQ_SCALE);
    int w  = __reduce_add_sync(0xFFFFFFFFu, si);

    __shared__ int warp_sums[8];
    const int warp = tid >> 5;
    const int lane = tid & 31;
    if (lane == 0) warp_sums[warp] = w;
    __syncthreads();

    if (tid == 0) {
        int ti = warp_sums[0] + warp_sums[1] + warp_sums[2] + warp_sums[3]
               + warp_sums[4] + warp_sums[5] + warp_sums[6] + warp_sums[7];
        float t = (float)ti * TQ_INV;               // row sum
        float part = -(1.0f / (t + 0.5f)) * inv_B;  // in [-1/32, 0)

        // Wait (usually already satisfied) for node A's zero of out[0],
        // then fire-and-forget accumulate. Return unused -> REDG, no stall.
        cudaGridDependencySynchronize();
        atomicAdd(out, part);
    }
}

extern "C" void kernel_launch(void* const* d_in, const int* in_sizes, int n_in,
                              void* d_out, int out_size) {
    const float* x = (const float*)d_in[0];
    float* out = (float*)d_out;

    const int total = in_sizes[0];   // B * N = 65536
    const int N = 2048;
    const int B = total / N;         // 32 == RB

    rankloss_init<<<1, 1>>>(out);

    cudaLaunchConfig_t cfg = {};
    cfg.gridDim  = dim3((unsigned)B, 1, 1);
    cfg.blockDim = dim3(256, 1, 1);
    cfg.dynamicSmemBytes = 0;
    cfg.stream = 0;  // legacy default stream, same as <<<>>> above
    cudaLaunchAttribute attr[1];
    attr[0].id = cudaLaunchAttributeProgrammaticStreamSerialization;
    attr[0].val.programmaticStreamSerializationAllowed = 1;
    cfg.attrs = attr;
    cfg.numAttrs = 1;

    float inv_B = 1.0f / (float)B;
    cudaLaunchKernelEx(&cfg, rankloss_main, x, out, inv_B);
}